// round 1
// baseline (speedup 1.0000x reference)
#include <cuda_runtime.h>
#include <cub/cub.cuh>

// ---------------------------------------------------------------------------
// Graph U-Net forward (GCNConv + BatchNorm + ReLU, TopKPooling, unpool, sigmoid)
// Sizes fixed by the problem.
// ---------------------------------------------------------------------------
#define cN0 80000
#define cN1 40000
#define cN2 20000
#define cN3 10000
#define cNE 1280000
#define HID 64
#define BN_EPS 1e-5f
#define TPB 256

// ------------------------- static device scratch ---------------------------
__device__ __align__(16) float g_X0[cN0 * HID];   // xs[0] (n=80000)
__device__ __align__(16) float g_X1[cN1 * HID];   // xs[1] (n=40000)
__device__ __align__(16) float g_X2[cN2 * HID];   // xs[2] (n=20000)
__device__ __align__(16) float g_XA[cN0 * HID];   // current x / pooled x
__device__ __align__(16) float g_H [cN0 * HID];   // h = x @ W
__device__ __align__(16) float g_AGG[cN0 * HID];  // agg / y buffer
__device__ float g_deg[cN0];                      // deg -> dinv (in place)
__device__ float g_keys[cN0];
__device__ float g_keysOut[cN0];
__device__ int   g_idx[cN0];
__device__ int   g_perm0[cN0];                    // sorted idx level 0 (use first 40000)
__device__ int   g_perm1[cN1];
__device__ int   g_perm2[cN2];
__device__ int   g_map[cN0];
__device__ int   g_src1[cNE], g_dst1[cNE];
__device__ int   g_src2[cNE], g_dst2[cNE];
__device__ int   g_src3[cNE], g_dst3[cNE];
__device__ float g_ew1[cNE], g_ew2[cNE], g_ew3[cNE];
__device__ float g_stats[2 * HID + 1];            // [0:64) sum, [64:128) sumsq, [128] ||pw||
__device__ float g_h1[cN0];                       // final conv h (1 channel)
__device__ float g_agg1[cN0];
__device__ __align__(256) unsigned char g_cubtmp[16 * 1024 * 1024];

// ------------------------------- kernels -----------------------------------
__global__ void k_zerof(float* __restrict__ p, int n) {
    for (int t = blockIdx.x * blockDim.x + threadIdx.x; t < n; t += gridDim.x * blockDim.x)
        p[t] = 0.f;
}

// H[n, cout] = X[n, cin] @ W[cin, cout]; cin,cout <= 64
__global__ void k_matmul(const float* __restrict__ X, const float* __restrict__ W,
                         float* __restrict__ H, int n, int cin, int cout) {
    __shared__ float sW[HID * HID];
    for (int i = threadIdx.x; i < cin * cout; i += blockDim.x) sW[i] = W[i];
    __syncthreads();
    int total = n * cout;
    for (int t = blockIdx.x * blockDim.x + threadIdx.x; t < total; t += gridDim.x * blockDim.x) {
        int r = t / cout, c = t - r * cout;
        const float* xr = X + (long long)r * cin;
        float acc = 0.f;
        #pragma unroll 8
        for (int k = 0; k < cin; k++) acc += xr[k] * sW[k * cout + c];
        H[t] = acc;
    }
}

__global__ void k_deg(const int* __restrict__ dst, const float* __restrict__ ew,
                      float* __restrict__ deg, int ne) {
    for (int t = blockIdx.x * blockDim.x + threadIdx.x; t < ne; t += gridDim.x * blockDim.x) {
        float w = ew ? ew[t] : 1.f;
        if (w != 0.f) atomicAdd(&deg[dst[t]], w);
    }
}

__global__ void k_dinv(float* __restrict__ deg, int n, float fill) {
    for (int t = blockIdx.x * blockDim.x + threadIdx.x; t < n; t += gridDim.x * blockDim.x)
        deg[t] = rsqrtf(deg[t] + fill);
}

// one warp per edge, each lane handles 2 channels (float2)
__global__ void k_edge_agg(const int* __restrict__ src, const int* __restrict__ dst,
                           const float* __restrict__ ew, const float* __restrict__ dinv,
                           const float* __restrict__ H, float* __restrict__ AGG, int ne) {
    int lane = threadIdx.x & 31;
    int w0 = (blockIdx.x * blockDim.x + threadIdx.x) >> 5;
    int nw = (gridDim.x * blockDim.x) >> 5;
    for (int e = w0; e < ne; e += nw) {
        int s = 0, d = 0;
        float cf = 0.f;
        if (lane == 0) {
            float w = ew ? ew[e] : 1.f;
            if (w != 0.f) {
                s = src[e];
                d = dst[e];
                cf = dinv[s] * w * dinv[d];
            }
        }
        cf = __shfl_sync(0xffffffffu, cf, 0);
        if (cf != 0.f) {
            s = __shfl_sync(0xffffffffu, s, 0);
            d = __shfl_sync(0xffffffffu, d, 0);
            float2 hv = reinterpret_cast<const float2*>(H)[(long long)s * 32 + lane];
            atomicAdd(&AGG[(long long)d * HID + 2 * lane],     cf * hv.x);
            atomicAdd(&AGG[(long long)d * HID + 2 * lane + 1], cf * hv.y);
        }
    }
}

// y = agg + fill*dinv^2*h (in place into Y==AGG ok), accumulate per-channel sum/sumsq.
// Requires gridDim.x*blockDim.x % 64 == 0 so each thread stays on one channel.
__global__ void k_combine_stats(const float* __restrict__ AGGi, const float* __restrict__ H,
                                const float* __restrict__ dinv, float* __restrict__ Y,
                                float* __restrict__ stats, float fill, int n) {
    int tid = blockIdx.x * blockDim.x + threadIdx.x;
    int c = tid & 63;
    float s = 0.f, q = 0.f;
    int total = n * HID;
    for (int t = tid; t < total; t += gridDim.x * blockDim.x) {
        int r = t >> 6;
        float di = dinv[r];
        float y = AGGi[t] + fill * di * di * H[t];
        Y[t] = y;
        s += y;
        q += y * y;
    }
    atomicAdd(&stats[c], s);
    atomicAdd(&stats[HID + c], q);
}

__global__ void k_bn_relu(const float* __restrict__ Y, const float* __restrict__ gamma,
                          const float* __restrict__ beta, const float* __restrict__ stats,
                          float* __restrict__ Xo, int n) {
    float inv_n = 1.f / (float)n;
    int total = n * HID;
    for (int t = blockIdx.x * blockDim.x + threadIdx.x; t < total; t += gridDim.x * blockDim.x) {
        int c = t & 63;
        float mu = stats[c] * inv_n;
        float var = stats[HID + c] * inv_n - mu * mu;
        float v = gamma[c] * (Y[t] - mu) * rsqrtf(var + BN_EPS) + beta[c];
        Xo[t] = v > 0.f ? v : 0.f;
    }
}

__global__ void k_pwnorm(const float* __restrict__ pw, float* __restrict__ stats) {
    __shared__ float sh[HID];
    float v = pw[threadIdx.x];
    sh[threadIdx.x] = v * v;
    __syncthreads();
    for (int o = 32; o > 0; o >>= 1) {
        if (threadIdx.x < o) sh[threadIdx.x] += sh[threadIdx.x + o];
        __syncthreads();
    }
    if (threadIdx.x == 0) stats[2 * HID] = sqrtf(sh[0]);
}

// score[r] = relu(dot(x[r], pw) / ||pw||); one warp per row
__global__ void k_score(const float* __restrict__ X, const float* __restrict__ pw,
                        const float* __restrict__ stats, float* __restrict__ keys,
                        int* __restrict__ idx, int n) {
    int lane = threadIdx.x & 31;
    int w0 = (blockIdx.x * blockDim.x + threadIdx.x) >> 5;
    int nw = (gridDim.x * blockDim.x) >> 5;
    for (int r = w0; r < n; r += nw) {
        float v = X[(long long)r * HID + lane] * pw[lane]
                + X[(long long)r * HID + 32 + lane] * pw[32 + lane];
        #pragma unroll
        for (int o = 16; o > 0; o >>= 1) v += __shfl_xor_sync(0xffffffffu, v, o);
        if (lane == 0) {
            float s = v / stats[2 * HID];
            keys[r] = s > 0.f ? s : 0.f;
            idx[r] = r;
        }
    }
}

// xk[i] = x[perm[i]] * sc[i]
__global__ void k_gather(const float* __restrict__ X, const int* __restrict__ perm,
                         const float* __restrict__ sc, float* __restrict__ Xk, int k) {
    int total = k * HID;
    for (int t = blockIdx.x * blockDim.x + threadIdx.x; t < total; t += gridDim.x * blockDim.x) {
        int i = t >> 6, c = t & 63;
        Xk[t] = X[(long long)perm[i] * HID + c] * sc[i];
    }
}

__global__ void k_mapinit(int* __restrict__ map, int n) {
    for (int t = blockIdx.x * blockDim.x + threadIdx.x; t < n; t += gridDim.x * blockDim.x)
        map[t] = -1;
}
__global__ void k_mapset(int* __restrict__ map, const int* __restrict__ perm, int k) {
    for (int t = blockIdx.x * blockDim.x + threadIdx.x; t < k; t += gridDim.x * blockDim.x)
        map[perm[t]] = t;
}

__global__ void k_remap(const int* __restrict__ srcO, const int* __restrict__ dstO,
                        const float* __restrict__ ewO, const int* __restrict__ map,
                        int* __restrict__ srcN, int* __restrict__ dstN,
                        float* __restrict__ ewN, int ne) {
    for (int t = blockIdx.x * blockDim.x + threadIdx.x; t < ne; t += gridDim.x * blockDim.x) {
        int ns = map[srcO[t]];
        int nd = map[dstO[t]];
        bool valid = (ns >= 0) && (nd >= 0);
        float w = ewO ? ewO[t] : 1.f;
        srcN[t] = valid ? ns : 0;
        dstN[t] = valid ? nd : 0;
        ewN[t]  = valid ? w : 0.f;
    }
}

// res[perm[i]] += xs[i]  (perm entries unique -> no atomics)
__global__ void k_unpool(float* __restrict__ Xres, const float* __restrict__ Xs,
                         const int* __restrict__ perm, int k) {
    int total = k * HID;
    for (int t = blockIdx.x * blockDim.x + threadIdx.x; t < total; t += gridDim.x * blockDim.x) {
        int i = t >> 6, c = t & 63;
        Xres[(long long)perm[i] * HID + c] += Xs[t];
    }
}

// final 1-channel aggregation (ew == 1 everywhere on level 0)
__global__ void k_edge_agg1(const int* __restrict__ src, const int* __restrict__ dst,
                            const float* __restrict__ dinv, const float* __restrict__ h,
                            float* __restrict__ agg, int ne) {
    for (int t = blockIdx.x * blockDim.x + threadIdx.x; t < ne; t += gridDim.x * blockDim.x) {
        int s = src[t], d = dst[t];
        atomicAdd(&agg[d], dinv[s] * dinv[d] * h[s]);
    }
}

__global__ void k_final(const float* __restrict__ agg, const float* __restrict__ h,
                        const float* __restrict__ dinv, float* __restrict__ out, int n) {
    for (int t = blockIdx.x * blockDim.x + threadIdx.x; t < n; t += gridDim.x * blockDim.x) {
        float di = dinv[t];
        float v = agg[t] + di * di * h[t];
        out[t] = 1.f / (1.f + expf(-v));
    }
}

// ------------------------------- host side ---------------------------------
static inline int nblk(long long n) { return (int)((n + TPB - 1) / TPB); }

struct DevPtrs {
    float *X0, *X1, *X2, *XA, *H, *AGG, *deg, *keys, *keysOut, *stats, *h1, *agg1;
    float *ew1, *ew2, *ew3;
    int *idx, *perm0, *perm1, *perm2, *map;
    int *src1, *dst1, *src2, *dst2, *src3, *dst3;
    void* cubtmp;
};

static void get_ptrs(DevPtrs& p) {
    void* q;
    cudaGetSymbolAddress(&q, g_X0);   p.X0 = (float*)q;
    cudaGetSymbolAddress(&q, g_X1);   p.X1 = (float*)q;
    cudaGetSymbolAddress(&q, g_X2);   p.X2 = (float*)q;
    cudaGetSymbolAddress(&q, g_XA);   p.XA = (float*)q;
    cudaGetSymbolAddress(&q, g_H);    p.H = (float*)q;
    cudaGetSymbolAddress(&q, g_AGG);  p.AGG = (float*)q;
    cudaGetSymbolAddress(&q, g_deg);  p.deg = (float*)q;
    cudaGetSymbolAddress(&q, g_keys); p.keys = (float*)q;
    cudaGetSymbolAddress(&q, g_keysOut); p.keysOut = (float*)q;
    cudaGetSymbolAddress(&q, g_stats); p.stats = (float*)q;
    cudaGetSymbolAddress(&q, g_h1);   p.h1 = (float*)q;
    cudaGetSymbolAddress(&q, g_agg1); p.agg1 = (float*)q;
    cudaGetSymbolAddress(&q, g_ew1);  p.ew1 = (float*)q;
    cudaGetSymbolAddress(&q, g_ew2);  p.ew2 = (float*)q;
    cudaGetSymbolAddress(&q, g_ew3);  p.ew3 = (float*)q;
    cudaGetSymbolAddress(&q, g_idx);  p.idx = (int*)q;
    cudaGetSymbolAddress(&q, g_perm0); p.perm0 = (int*)q;
    cudaGetSymbolAddress(&q, g_perm1); p.perm1 = (int*)q;
    cudaGetSymbolAddress(&q, g_perm2); p.perm2 = (int*)q;
    cudaGetSymbolAddress(&q, g_map);  p.map = (int*)q;
    cudaGetSymbolAddress(&q, g_src1); p.src1 = (int*)q;
    cudaGetSymbolAddress(&q, g_dst1); p.dst1 = (int*)q;
    cudaGetSymbolAddress(&q, g_src2); p.src2 = (int*)q;
    cudaGetSymbolAddress(&q, g_dst2); p.dst2 = (int*)q;
    cudaGetSymbolAddress(&q, g_src3); p.src3 = (int*)q;
    cudaGetSymbolAddress(&q, g_dst3); p.dst3 = (int*)q;
    cudaGetSymbolAddress(&q, g_cubtmp); p.cubtmp = q;
}

// one GCN conv + BatchNorm + ReLU
static void gcn_block(const DevPtrs& p, const float* Xin, const float* W,
                      const float* gamma, const float* beta, int n, int cin,
                      const int* src, const int* dst, const float* ew, float fill,
                      float* Xout) {
    k_matmul<<<nblk((long long)n * HID), TPB>>>(Xin, W, p.H, n, cin, HID);
    k_zerof<<<nblk(n), TPB>>>(p.deg, n);
    k_deg<<<nblk(cNE), TPB>>>(dst, ew, p.deg, cNE);
    k_dinv<<<nblk(n), TPB>>>(p.deg, n, fill);
    k_zerof<<<nblk((long long)n * HID), TPB>>>(p.AGG, n * HID);
    k_edge_agg<<<(cNE * 32) / TPB, TPB>>>(src, dst, ew, p.deg, p.H, p.AGG, cNE);
    k_zerof<<<1, 2 * HID>>>(p.stats, 2 * HID);
    k_combine_stats<<<512, TPB>>>(p.AGG, p.H, p.deg, p.AGG, p.stats, fill, n);
    k_bn_relu<<<nblk((long long)n * HID), TPB>>>(p.AGG, gamma, beta, p.stats, Xout, n);
}

// TopK pooling: scores, stable descending sort, gather*scale into XA, edge remap
static void topk_pool(const DevPtrs& p, const float* X, int n, int k, const float* pw,
                      const int* srcO, const int* dstO, const float* ewO,
                      int* srcN, int* dstN, float* ewN, int* permOut) {
    k_pwnorm<<<1, HID>>>(pw, p.stats);
    k_score<<<nblk((long long)n * 32), TPB>>>(X, pw, p.stats, p.keys, p.idx, n);
    size_t tmp_bytes = 0;
    cub::DeviceRadixSort::SortPairsDescending(nullptr, tmp_bytes, p.keys, p.keysOut,
                                              p.idx, permOut, n, 0, 32, (cudaStream_t)0);
    cub::DeviceRadixSort::SortPairsDescending(p.cubtmp, tmp_bytes, p.keys, p.keysOut,
                                              p.idx, permOut, n, 0, 32, (cudaStream_t)0);
    k_gather<<<nblk((long long)k * HID), TPB>>>(X, permOut, p.keysOut, p.XA, k);
    k_mapinit<<<nblk(n), TPB>>>(p.map, n);
    k_mapset<<<nblk(k), TPB>>>(p.map, permOut, k);
    k_remap<<<nblk(cNE), TPB>>>(srcO, dstO, ewO, p.map, srcN, dstN, ewN, cNE);
}

extern "C" void kernel_launch(void* const* d_in, const int* in_sizes, int n_in,
                              void* d_out, int out_size) {
    const float* x_in = (const float*)d_in[0];
    const int* ei     = (const int*)d_in[1];
    const int* src0 = ei;
    const int* dst0 = ei + cNE;
    const float* Wd[4]  = {(const float*)d_in[2],  (const float*)d_in[5],
                           (const float*)d_in[8],  (const float*)d_in[11]};
    const float* gd[4]  = {(const float*)d_in[3],  (const float*)d_in[6],
                           (const float*)d_in[9],  (const float*)d_in[12]};
    const float* bd[4]  = {(const float*)d_in[4],  (const float*)d_in[7],
                           (const float*)d_in[10], (const float*)d_in[13]};
    const float* pw[3]  = {(const float*)d_in[14], (const float*)d_in[15],
                           (const float*)d_in[16]};
    const float* Wu[2]  = {(const float*)d_in[17], (const float*)d_in[20]};
    const float* gu[2]  = {(const float*)d_in[18], (const float*)d_in[21]};
    const float* bu[2]  = {(const float*)d_in[19], (const float*)d_in[22]};
    const float* Wout   = (const float*)d_in[23];

    DevPtrs p;
    get_ptrs(p);

    // ---- down path ----
    // block 0 (3 -> 64) on the full graph (ew = ones)
    gcn_block(p, x_in, Wd[0], gd[0], bd[0], cN0, 3, src0, dst0, nullptr, 2.0f, p.X0);

    // pool 0 (80000 -> 40000) + block 1
    topk_pool(p, p.X0, cN0, cN1, pw[0], src0, dst0, nullptr,
              p.src1, p.dst1, p.ew1, p.perm0);
    gcn_block(p, p.XA, Wd[1], gd[1], bd[1], cN1, HID, p.src1, p.dst1, p.ew1, 2.0f, p.X1);

    // pool 1 (40000 -> 20000) + block 2
    topk_pool(p, p.X1, cN1, cN2, pw[1], p.src1, p.dst1, p.ew1,
              p.src2, p.dst2, p.ew2, p.perm1);
    gcn_block(p, p.XA, Wd[2], gd[2], bd[2], cN2, HID, p.src2, p.dst2, p.ew2, 2.0f, p.X2);

    // pool 2 (20000 -> 10000) + block 3
    topk_pool(p, p.X2, cN2, cN3, pw[2], p.src2, p.dst2, p.ew2,
              p.src3, p.dst3, p.ew3, p.perm2);
    gcn_block(p, p.XA, Wd[3], gd[3], bd[3], cN3, HID, p.src3, p.dst3, p.ew3, 2.0f, p.XA);

    // ---- up path ----
    // i=0: unpool into X2 (n=20000), block with Wu0 over level-2 edges
    k_unpool<<<nblk((long long)cN3 * HID), TPB>>>(p.X2, p.XA, p.perm2, cN3);
    gcn_block(p, p.X2, Wu[0], gu[0], bu[0], cN2, HID, p.src2, p.dst2, p.ew2, 2.0f, p.XA);

    // i=1: unpool into X1 (n=40000), block with Wu1 over level-1 edges
    k_unpool<<<nblk((long long)cN2 * HID), TPB>>>(p.X1, p.XA, p.perm1, cN2);
    gcn_block(p, p.X1, Wu[1], gu[1], bu[1], cN1, HID, p.src1, p.dst1, p.ew1, 2.0f, p.XA);

    // i=2: unpool into X0 (n=80000), final sigmoid GCN conv (fill = 1.0, 64 -> 1)
    k_unpool<<<nblk((long long)cN1 * HID), TPB>>>(p.X0, p.XA, p.perm0, cN1);
    k_matmul<<<nblk(cN0), TPB>>>(p.X0, Wout, p.h1, cN0, HID, 1);
    k_zerof<<<nblk(cN0), TPB>>>(p.deg, cN0);
    k_deg<<<nblk(cNE), TPB>>>(dst0, nullptr, p.deg, cNE);
    k_dinv<<<nblk(cN0), TPB>>>(p.deg, cN0, 1.0f);
    k_zerof<<<nblk(cN0), TPB>>>(p.agg1, cN0);
    k_edge_agg1<<<nblk(cNE), TPB>>>(src0, dst0, p.deg, p.h1, p.agg1, cNE);
    k_final<<<nblk(cN0), TPB>>>(p.agg1, p.h1, p.deg, (float*)d_out, cN0);
}

// round 2
// speedup vs baseline: 2.0994x; 2.0994x over previous
#include <cuda_runtime.h>
#include <cub/cub.cuh>

// ---------------------------------------------------------------------------
// Graph U-Net forward, CSR-based aggregation, compacted pooled edge lists.
// ---------------------------------------------------------------------------
#define cN0 80000
#define cN1 40000
#define cN2 20000
#define cN3 10000
#define cNE 1280000
#define HID 64
#define BN_EPS 1e-5f
#define TPB 256
#define EDGE_GRID 5000   // ceil(cNE / TPB)

// ------------------------- static device scratch ---------------------------
__device__ __align__(16) float g_X0[cN0 * HID];
__device__ __align__(16) float g_X1[cN1 * HID];
__device__ __align__(16) float g_X2[cN2 * HID];
__device__ __align__(16) float g_XA[cN1 * HID];   // block3 / up-block outputs (max n=40000)
__device__ __align__(16) float g_H [cN0 * HID];
__device__ __align__(16) float g_Y [cN0 * HID];
__device__ int   g_deg[cN0 + 1];
__device__ int   g_cursor[cN0];
__device__ int   g_rs0[cN0 + 1];
__device__ int   g_rs1[cN1 + 1];
__device__ int   g_rs2[cN2 + 1];
__device__ int   g_rs3[cN3 + 1];
__device__ float g_dinv0_2[cN0], g_dinv0_1[cN0];
__device__ float g_dinv1[cN1], g_dinv2[cN2], g_dinv3[cN3];
__device__ int   g_csr0[cNE], g_csr1[cNE], g_csr2[cNE], g_csr3[cNE];
__device__ int   g_src1[cNE], g_dst1[cNE];
__device__ int   g_src2[cNE], g_dst2[cNE];
__device__ int   g_src3[cNE], g_dst3[cNE];
__device__ int   g_cnt[3];
__device__ float g_keys[cN0];
__device__ float g_keysOut[cN0];
__device__ int   g_idx[cN0];
__device__ int   g_perm0[cN0], g_perm1[cN1], g_perm2[cN2];
__device__ int   g_map[cN0];
__device__ float g_stats[2 * HID + 1];   // [0:64) sum, [64:128) sumsq, [128] ||pw||
__device__ float g_h1[cN0];
__device__ __align__(256) unsigned char g_cubtmp[16 * 1024 * 1024];

// ------------------------------- kernels -----------------------------------
__global__ void k_zerof(float* __restrict__ p, int n) {
    int t = blockIdx.x * blockDim.x + threadIdx.x;
    if (t < n) p[t] = 0.f;
}
__global__ void k_zeroi(int* __restrict__ p, int n) {
    int t = blockIdx.x * blockDim.x + threadIdx.x;
    if (t < n) p[t] = 0;
}
__global__ void k_copyi(const int* __restrict__ a, int* __restrict__ b, int n) {
    int t = blockIdx.x * blockDim.x + threadIdx.x;
    if (t < n) b[t] = a[t];
}

// histogram of dst over the (possibly device-counted) edge list
__global__ void k_hist(const int* __restrict__ dstC, int* __restrict__ deg,
                       const int* __restrict__ cntp, int nfix) {
    int cnt = cntp ? *cntp : nfix;
    for (int t = blockIdx.x * blockDim.x + threadIdx.x; t < cnt; t += gridDim.x * blockDim.x)
        atomicAdd(&deg[dstC[t]], 1);
}

__global__ void k_dinv_i(const int* __restrict__ deg, float* __restrict__ dinv,
                         int n, float fill) {
    int t = blockIdx.x * blockDim.x + threadIdx.x;
    if (t < n) dinv[t] = rsqrtf((float)deg[t] + fill);
}

__global__ void k_scatter(const int* __restrict__ srcC, const int* __restrict__ dstC,
                          int* __restrict__ cursor, int* __restrict__ csr,
                          const int* __restrict__ cntp, int nfix) {
    int cnt = cntp ? *cntp : nfix;
    for (int t = blockIdx.x * blockDim.x + threadIdx.x; t < cnt; t += gridDim.x * blockDim.x) {
        int pos = atomicAdd(&cursor[dstC[t]], 1);
        csr[pos] = srcC[t];
    }
}

// compact remap: keep only edges whose both endpoints survive pooling
__global__ void k_remapc(const int* __restrict__ srcP, const int* __restrict__ dstP,
                         const int* __restrict__ map, int* __restrict__ srcN,
                         int* __restrict__ dstN, int* __restrict__ cntN,
                         const int* __restrict__ cntp, int nfix) {
    int cnt = cntp ? *cntp : nfix;
    for (int t = blockIdx.x * blockDim.x + threadIdx.x; t < cnt; t += gridDim.x * blockDim.x) {
        int ns = map[srcP[t]];
        int nd = map[dstP[t]];
        if ((ns >= 0) && (nd >= 0)) {
            int p = atomicAdd(cntN, 1);
            srcN[p] = ns;
            dstN[p] = nd;
        }
    }
}

// H[r, q..q+3] = (X[perm?[r]] * sc?[r]) @ W ; 4 outputs per thread
__global__ void k_matmul4(const float* __restrict__ X, const float* __restrict__ W,
                          const int* __restrict__ perm, const float* __restrict__ sc,
                          float* __restrict__ H, int n, int cin) {
    __shared__ float sW[HID * HID];
    for (int i = threadIdx.x; i < cin * HID; i += blockDim.x) sW[i] = W[i];
    __syncthreads();
    int t = blockIdx.x * blockDim.x + threadIdx.x;
    if (t >= n * 16) return;
    int r = t >> 4, q = (t & 15) * 4;
    long long ridx = r;
    float scale = 1.f;
    if (perm) { ridx = perm[r]; scale = sc[r]; }
    const float* xp = X + ridx * cin;
    float a0 = 0.f, a1 = 0.f, a2 = 0.f, a3 = 0.f;
    for (int k = 0; k < cin; k++) {
        float xv = xp[k] * scale;
        const float* w = sW + k * HID + q;
        a0 += xv * w[0]; a1 += xv * w[1]; a2 += xv * w[2]; a3 += xv * w[3];
    }
    reinterpret_cast<float4*>(H)[(long long)r * 16 + (q >> 2)] = make_float4(a0, a1, a2, a3);
}

// warp per dst row: Y[d] = sum_nb cf*H[s] + fill*dinv[d]^2*H[d]; accumulate BN stats
__global__ void k_csr_agg_bn(const int* __restrict__ rs, const int* __restrict__ csr,
                             const float* __restrict__ dinv, const float* __restrict__ H,
                             float* __restrict__ Y, float* __restrict__ stats,
                             float fill, int n) {
    __shared__ float sh[128];
    if (threadIdx.x < 128) sh[threadIdx.x] = 0.f;
    __syncthreads();
    int lane = threadIdx.x & 31;
    int d = (blockIdx.x * blockDim.x + threadIdx.x) >> 5;
    float s0 = 0.f, s1 = 0.f, q0 = 0.f, q1 = 0.f;
    if (d < n) {
        int r0 = rs[d], r1 = rs[d + 1];
        float dd = dinv[d];
        float a0 = 0.f, a1 = 0.f;
        int j = r0;
        for (; j + 2 <= r1; j += 2) {
            int sA = csr[j], sB = csr[j + 1];
            float cfA = dinv[sA] * dd;
            float cfB = dinv[sB] * dd;
            float2 hA = reinterpret_cast<const float2*>(H)[(long long)sA * 32 + lane];
            float2 hB = reinterpret_cast<const float2*>(H)[(long long)sB * 32 + lane];
            a0 += cfA * hA.x + cfB * hB.x;
            a1 += cfA * hA.y + cfB * hB.y;
        }
        if (j < r1) {
            int sA = csr[j];
            float cfA = dinv[sA] * dd;
            float2 hA = reinterpret_cast<const float2*>(H)[(long long)sA * 32 + lane];
            a0 += cfA * hA.x;
            a1 += cfA * hA.y;
        }
        float2 hd = reinterpret_cast<const float2*>(H)[(long long)d * 32 + lane];
        float sf = fill * dd * dd;
        float y0 = a0 + sf * hd.x;
        float y1 = a1 + sf * hd.y;
        reinterpret_cast<float2*>(Y)[(long long)d * 32 + lane] = make_float2(y0, y1);
        s0 = y0; s1 = y1; q0 = y0 * y0; q1 = y1 * y1;
    }
    atomicAdd(&sh[2 * lane],      s0);
    atomicAdd(&sh[2 * lane + 1],  s1);
    atomicAdd(&sh[64 + 2 * lane], q0);
    atomicAdd(&sh[65 + 2 * lane], q1);
    __syncthreads();
    if (threadIdx.x < 128) atomicAdd(&stats[threadIdx.x], sh[threadIdx.x]);
}

__global__ void k_bn_relu(const float* __restrict__ Y, const float* __restrict__ gamma,
                          const float* __restrict__ beta, const float* __restrict__ stats,
                          float* __restrict__ Xo, int n) {
    float inv_n = 1.f / (float)n;
    int total = n * HID;
    int t = blockIdx.x * blockDim.x + threadIdx.x;
    if (t >= total) return;
    int c = t & 63;
    float mu = stats[c] * inv_n;
    float var = stats[HID + c] * inv_n - mu * mu;
    float v = gamma[c] * (Y[t] - mu) * rsqrtf(var + BN_EPS) + beta[c];
    Xo[t] = v > 0.f ? v : 0.f;
}

__global__ void k_pwnorm(const float* __restrict__ pw, float* __restrict__ stats) {
    __shared__ float sh[HID];
    float v = pw[threadIdx.x];
    sh[threadIdx.x] = v * v;
    __syncthreads();
    for (int o = 32; o > 0; o >>= 1) {
        if (threadIdx.x < o) sh[threadIdx.x] += sh[threadIdx.x + o];
        __syncthreads();
    }
    if (threadIdx.x == 0) stats[2 * HID] = sqrtf(sh[0]);
}

__global__ void k_score(const float* __restrict__ X, const float* __restrict__ pw,
                        const float* __restrict__ stats, float* __restrict__ keys,
                        int* __restrict__ idx, int n) {
    int lane = threadIdx.x & 31;
    int r = (blockIdx.x * blockDim.x + threadIdx.x) >> 5;
    if (r >= n) return;
    float v = X[(long long)r * HID + lane] * pw[lane]
            + X[(long long)r * HID + 32 + lane] * pw[32 + lane];
    #pragma unroll
    for (int o = 16; o > 0; o >>= 1) v += __shfl_xor_sync(0xffffffffu, v, o);
    if (lane == 0) {
        float s = v / stats[2 * HID];
        keys[r] = s > 0.f ? s : 0.f;
        idx[r] = r;
    }
}

__global__ void k_mapinit(int* __restrict__ map, int n) {
    int t = blockIdx.x * blockDim.x + threadIdx.x;
    if (t < n) map[t] = -1;
}
__global__ void k_mapset(int* __restrict__ map, const int* __restrict__ perm, int k) {
    int t = blockIdx.x * blockDim.x + threadIdx.x;
    if (t < k) map[perm[t]] = t;
}

// res[perm[i]] += xs[i]   (perm unique)
__global__ void k_unpool(float* __restrict__ Xres, const float* __restrict__ Xs,
                         const int* __restrict__ perm, int k) {
    int t = blockIdx.x * blockDim.x + threadIdx.x;
    if (t >= k * HID) return;
    int i = t >> 6, c = t & 63;
    Xres[(long long)perm[i] * HID + c] += Xs[t];
}

// h[r] = X[r,:] . W  (cout = 1)
__global__ void k_matmul1(const float* __restrict__ X, const float* __restrict__ W,
                          float* __restrict__ h, int n) {
    __shared__ float sW[HID];
    if (threadIdx.x < HID) sW[threadIdx.x] = W[threadIdx.x];
    __syncthreads();
    int r = blockIdx.x * blockDim.x + threadIdx.x;
    if (r >= n) return;
    const float4* xp = reinterpret_cast<const float4*>(X + (long long)r * HID);
    float acc = 0.f;
    #pragma unroll
    for (int k = 0; k < 16; k++) {
        float4 x = xp[k];
        acc += x.x * sW[4 * k] + x.y * sW[4 * k + 1]
             + x.z * sW[4 * k + 2] + x.w * sW[4 * k + 3];
    }
    h[r] = acc;
}

// warp per dst: out[d] = sigmoid(dinv[d]*sum(dinv[s]h[s]) + dinv[d]^2 h[d])
__global__ void k_csr_final(const int* __restrict__ rs, const int* __restrict__ csr,
                            const float* __restrict__ dinv, const float* __restrict__ h,
                            float* __restrict__ out, int n) {
    int lane = threadIdx.x & 31;
    int d = (blockIdx.x * blockDim.x + threadIdx.x) >> 5;
    if (d >= n) return;
    int r0 = rs[d], r1 = rs[d + 1];
    float acc = 0.f;
    for (int j = r0 + lane; j < r1; j += 32) {
        int s = csr[j];
        acc += dinv[s] * h[s];
    }
    #pragma unroll
    for (int o = 16; o > 0; o >>= 1) acc += __shfl_xor_sync(0xffffffffu, acc, o);
    if (lane == 0) {
        float dd = dinv[d];
        float v = dd * acc + dd * dd * h[d];
        out[d] = 1.f / (1.f + expf(-v));
    }
}

// ------------------------------- host side ---------------------------------
static inline int nblk(long long n) { return (int)((n + TPB - 1) / TPB); }

struct DevPtrs {
    float *X0, *X1, *X2, *XA, *H, *Y;
    int *deg, *cursor, *rs0, *rs1, *rs2, *rs3;
    float *dinv0_2, *dinv0_1, *dinv1, *dinv2, *dinv3;
    int *csr0, *csr1, *csr2, *csr3;
    int *src1, *dst1, *src2, *dst2, *src3, *dst3, *cnt;
    float *keys, *keysOut, *stats, *h1;
    int *idx, *perm0, *perm1, *perm2, *map;
    void* cubtmp;
};

#define GETP(sym, field, type) { void* q; cudaGetSymbolAddress(&q, sym); p.field = (type)q; }

static void get_ptrs(DevPtrs& p) {
    GETP(g_X0, X0, float*) GETP(g_X1, X1, float*) GETP(g_X2, X2, float*)
    GETP(g_XA, XA, float*) GETP(g_H, H, float*) GETP(g_Y, Y, float*)
    GETP(g_deg, deg, int*) GETP(g_cursor, cursor, int*)
    GETP(g_rs0, rs0, int*) GETP(g_rs1, rs1, int*) GETP(g_rs2, rs2, int*) GETP(g_rs3, rs3, int*)
    GETP(g_dinv0_2, dinv0_2, float*) GETP(g_dinv0_1, dinv0_1, float*)
    GETP(g_dinv1, dinv1, float*) GETP(g_dinv2, dinv2, float*) GETP(g_dinv3, dinv3, float*)
    GETP(g_csr0, csr0, int*) GETP(g_csr1, csr1, int*) GETP(g_csr2, csr2, int*) GETP(g_csr3, csr3, int*)
    GETP(g_src1, src1, int*) GETP(g_dst1, dst1, int*)
    GETP(g_src2, src2, int*) GETP(g_dst2, dst2, int*)
    GETP(g_src3, src3, int*) GETP(g_dst3, dst3, int*)
    GETP(g_cnt, cnt, int*)
    GETP(g_keys, keys, float*) GETP(g_keysOut, keysOut, float*)
    GETP(g_stats, stats, float*) GETP(g_h1, h1, float*)
    GETP(g_idx, idx, int*) GETP(g_perm0, perm0, int*) GETP(g_perm1, perm1, int*)
    GETP(g_perm2, perm2, int*) GETP(g_map, map, int*)
    GETP(g_cubtmp, cubtmp, void*)
}

// Build dst-CSR (+dinv) for one level. cntp==nullptr means fixed nfix edges.
static void build_csr(const DevPtrs& p, const int* srcC, const int* dstC,
                      const int* cntp, int nfix, int n, int* rs, int* csr,
                      float* dinvA, float fillA, float* dinvB, float fillB) {
    k_zeroi<<<nblk(n + 1), TPB>>>(p.deg, n + 1);
    k_hist<<<EDGE_GRID, TPB>>>(dstC, p.deg, cntp, nfix);
    k_dinv_i<<<nblk(n), TPB>>>(p.deg, dinvA, n, fillA);
    if (dinvB) k_dinv_i<<<nblk(n), TPB>>>(p.deg, dinvB, n, fillB);
    size_t tb = 0;
    cub::DeviceScan::ExclusiveSum(nullptr, tb, p.deg, rs, n + 1, (cudaStream_t)0);
    cub::DeviceScan::ExclusiveSum(p.cubtmp, tb, p.deg, rs, n + 1, (cudaStream_t)0);
    k_copyi<<<nblk(n), TPB>>>(rs, p.cursor, n);
    k_scatter<<<EDGE_GRID, TPB>>>(srcC, dstC, p.cursor, csr, cntp, nfix);
}

// GCN conv + BN + ReLU over a pre-built CSR
static void gcn_block(const DevPtrs& p, const float* Xin, const int* perm,
                      const float* sc, const float* W, const float* gamma,
                      const float* beta, int n, int cin, const int* rs,
                      const int* csr, const float* dinv, float* Xout) {
    k_matmul4<<<n / 16, TPB>>>(Xin, W, perm, sc, p.H, n, cin);
    k_zerof<<<1, 128>>>(p.stats, 128);
    k_csr_agg_bn<<<n / 8, TPB>>>(rs, csr, dinv, p.H, p.Y, p.stats, 2.0f, n);
    k_bn_relu<<<nblk((long long)n * HID), TPB>>>(p.Y, gamma, beta, p.stats, Xout, n);
}

// TopK pooling: scores + stable descending sort + map + compacted remap
static void topk_pool(const DevPtrs& p, const float* X, int n, int k, const float* pw,
                      const int* srcP, const int* dstP, const int* cntP, int nfixP,
                      int* srcN, int* dstN, int* cntN, int* permOut) {
    k_pwnorm<<<1, HID>>>(pw, p.stats);
    k_score<<<n / 8, TPB>>>(X, pw, p.stats, p.keys, p.idx, n);
    size_t tb = 0;
    cub::DeviceRadixSort::SortPairsDescending(nullptr, tb, p.keys, p.keysOut,
                                              p.idx, permOut, n, 0, 32, (cudaStream_t)0);
    cub::DeviceRadixSort::SortPairsDescending(p.cubtmp, tb, p.keys, p.keysOut,
                                              p.idx, permOut, n, 0, 32, (cudaStream_t)0);
    k_mapinit<<<nblk(n), TPB>>>(p.map, n);
    k_mapset<<<nblk(k), TPB>>>(p.map, permOut, k);
    k_zeroi<<<1, 1>>>(cntN, 1);
    k_remapc<<<EDGE_GRID, TPB>>>(srcP, dstP, p.map, srcN, dstN, cntN, cntP, nfixP);
}

extern "C" void kernel_launch(void* const* d_in, const int* in_sizes, int n_in,
                              void* d_out, int out_size) {
    const float* x_in = (const float*)d_in[0];
    const int* ei     = (const int*)d_in[1];
    const int* src0 = ei;
    const int* dst0 = ei + cNE;
    const float* Wd[4] = {(const float*)d_in[2],  (const float*)d_in[5],
                          (const float*)d_in[8],  (const float*)d_in[11]};
    const float* gd[4] = {(const float*)d_in[3],  (const float*)d_in[6],
                          (const float*)d_in[9],  (const float*)d_in[12]};
    const float* bd[4] = {(const float*)d_in[4],  (const float*)d_in[7],
                          (const float*)d_in[10], (const float*)d_in[13]};
    const float* pw[3] = {(const float*)d_in[14], (const float*)d_in[15],
                          (const float*)d_in[16]};
    const float* Wu[2] = {(const float*)d_in[17], (const float*)d_in[20]};
    const float* gu[2] = {(const float*)d_in[18], (const float*)d_in[21]};
    const float* bu[2] = {(const float*)d_in[19], (const float*)d_in[22]};
    const float* Wout  = (const float*)d_in[23];

    DevPtrs p;
    get_ptrs(p);

    // ---- level 0 CSR (used by block0 with fill=2 and the final conv with fill=1)
    build_csr(p, src0, dst0, nullptr, cNE, cN0, p.rs0, p.csr0,
              p.dinv0_2, 2.0f, p.dinv0_1, 1.0f);

    // ---- down path ----
    gcn_block(p, x_in, nullptr, nullptr, Wd[0], gd[0], bd[0], cN0, 3,
              p.rs0, p.csr0, p.dinv0_2, p.X0);

    topk_pool(p, p.X0, cN0, cN1, pw[0], src0, dst0, nullptr, cNE,
              p.src1, p.dst1, &p.cnt[0], p.perm0);
    build_csr(p, p.src1, p.dst1, &p.cnt[0], 0, cN1, p.rs1, p.csr1,
              p.dinv1, 2.0f, nullptr, 0.f);
    gcn_block(p, p.X0, p.perm0, p.keysOut, Wd[1], gd[1], bd[1], cN1, HID,
              p.rs1, p.csr1, p.dinv1, p.X1);

    topk_pool(p, p.X1, cN1, cN2, pw[1], p.src1, p.dst1, &p.cnt[0], 0,
              p.src2, p.dst2, &p.cnt[1], p.perm1);
    build_csr(p, p.src2, p.dst2, &p.cnt[1], 0, cN2, p.rs2, p.csr2,
              p.dinv2, 2.0f, nullptr, 0.f);
    gcn_block(p, p.X1, p.perm1, p.keysOut, Wd[2], gd[2], bd[2], cN2, HID,
              p.rs2, p.csr2, p.dinv2, p.X2);

    topk_pool(p, p.X2, cN2, cN3, pw[2], p.src2, p.dst2, &p.cnt[1], 0,
              p.src3, p.dst3, &p.cnt[2], p.perm2);
    build_csr(p, p.src3, p.dst3, &p.cnt[2], 0, cN3, p.rs3, p.csr3,
              p.dinv3, 2.0f, nullptr, 0.f);
    gcn_block(p, p.X2, p.perm2, p.keysOut, Wd[3], gd[3], bd[3], cN3, HID,
              p.rs3, p.csr3, p.dinv3, p.XA);

    // ---- up path ----
    k_unpool<<<nblk((long long)cN3 * HID), TPB>>>(p.X2, p.XA, p.perm2, cN3);
    gcn_block(p, p.X2, nullptr, nullptr, Wu[0], gu[0], bu[0], cN2, HID,
              p.rs2, p.csr2, p.dinv2, p.XA);

    k_unpool<<<nblk((long long)cN2 * HID), TPB>>>(p.X1, p.XA, p.perm1, cN2);
    gcn_block(p, p.X1, nullptr, nullptr, Wu[1], gu[1], bu[1], cN1, HID,
              p.rs1, p.csr1, p.dinv1, p.XA);

    k_unpool<<<nblk((long long)cN1 * HID), TPB>>>(p.X0, p.XA, p.perm0, cN1);
    k_matmul1<<<nblk(cN0), TPB>>>(p.X0, Wout, p.h1, cN0);
    k_csr_final<<<cN0 / 8, TPB>>>(p.rs0, p.csr0, p.dinv0_1, p.h1, (float*)d_out, cN0);
}

// round 3
// speedup vs baseline: 2.6037x; 1.2402x over previous
#include <cuda_runtime.h>
#include <cub/cub.cuh>

// ---------------------------------------------------------------------------
// Graph U-Net forward — CSR aggregation, fused BN/score, 2-stream overlap.
// ---------------------------------------------------------------------------
#define cN0 80000
#define cN1 40000
#define cN2 20000
#define cN3 10000
#define cNE 1280000
#define HID 64
#define BN_EPS 1e-5f
#define TPB 256
#define GRIDE 1184
#define FULLM 0xffffffffu

// ------------------------- static device scratch ---------------------------
__device__ __align__(16) float g_X0[cN0 * HID];
__device__ __align__(16) float g_X1[cN1 * HID];
__device__ __align__(16) float g_X2[cN2 * HID];
__device__ __align__(16) float g_XA[cN1 * HID];   // block3 out, up1 out
__device__ __align__(16) float g_XB[cN2 * HID];   // up0 out
__device__ __align__(16) float g_H [cN0 * HID];
__device__ __align__(16) float g_Y [cN0 * HID];
__device__ int   g_deg[cN0 + 1];
__device__ int   g_cursor[cN0];
__device__ int   g_rs0[cN0 + 1], g_rs1[cN1 + 1], g_rs2[cN2 + 1], g_rs3[cN3 + 1];
__device__ float g_dinv0_2[cN0], g_dinv0_1[cN0];
__device__ float g_dinv1[cN1], g_dinv2[cN2], g_dinv3[cN3];
__device__ int   g_csr0[cNE], g_csr1[cNE], g_csr2[cNE], g_csr3[cNE];
__device__ int   g_src1[cNE], g_dst1[cNE];
__device__ int   g_src2[cNE], g_dst2[cNE];
__device__ int   g_src3[cNE], g_dst3[cNE];
__device__ int   g_cnt[4];
__device__ float g_keys[cN0], g_keysOut[cN0];
__device__ int   g_idx[cN0];
__device__ int   g_perm0[cN0], g_perm1[cN1], g_perm2[cN2];
__device__ int   g_map0[cN0], g_map1[cN1], g_map2[cN2];
__device__ float g_stats[2 * HID];
__device__ float g_h1[cN0];
__device__ __align__(256) unsigned char g_cubtmp[16 * 1024 * 1024];

// ------------------------------- kernels -----------------------------------
__global__ void k_zeroi(int* __restrict__ p, int n) {
    int t = blockIdx.x * blockDim.x + threadIdx.x;
    if (t < n) p[t] = 0;
}

// level-0 dst histogram (fixed edge count)
__global__ void k_hist0(const int* __restrict__ dst, int* __restrict__ deg) {
    for (int t = blockIdx.x * blockDim.x + threadIdx.x; t < cNE; t += gridDim.x * blockDim.x)
        atomicAdd(&deg[dst[t]], 1);
}

// cursor[t]=rs[t]; dinv from CSR row extents (degree)
__global__ void k_prep(const int* __restrict__ rs, int* __restrict__ cursor,
                       float* __restrict__ dinvA, float fillA,
                       float* __restrict__ dinvB, float fillB, int n) {
    int t = blockIdx.x * blockDim.x + threadIdx.x;
    if (t >= n) return;
    int r0 = rs[t], r1 = rs[t + 1];
    cursor[t] = r0;
    float d = (float)(r1 - r0);
    dinvA[t] = rsqrtf(d + fillA);
    if (dinvB) dinvB[t] = rsqrtf(d + fillB);
}

__global__ void k_scatter(const int* __restrict__ srcC, const int* __restrict__ dstC,
                          int* __restrict__ cursor, int* __restrict__ csr,
                          const int* __restrict__ cntp, int nfix) {
    int cnt = cntp ? *cntp : nfix;
    for (int t = blockIdx.x * blockDim.x + threadIdx.x; t < cnt; t += gridDim.x * blockDim.x) {
        int pos = atomicAdd(&cursor[dstC[t]], 1);
        csr[pos] = srcC[t];
    }
}

// map[perm[t]] = t; one thread zeroes the next edge counter
__global__ void k_mapset(int* __restrict__ map, const int* __restrict__ perm,
                         int k, int* __restrict__ cntZ) {
    int t = blockIdx.x * blockDim.x + threadIdx.x;
    if (t == 0) *cntZ = 0;
    if (t < k) map[perm[t]] = t;
}

// compact remap + dst-degree histogram; warp-aggregated counter pushes
__global__ void k_remap_hist(const int* __restrict__ srcP, const int* __restrict__ dstP,
                             const int* __restrict__ map, int* __restrict__ srcN,
                             int* __restrict__ dstN, int* __restrict__ cntN,
                             int* __restrict__ deg, const int* __restrict__ cntp, int nfix) {
    int cnt = cntp ? *cntp : nfix;
    int lane = threadIdx.x & 31;
    int stride = gridDim.x * blockDim.x;
    for (int t = blockIdx.x * blockDim.x + threadIdx.x;; t += stride) {
        bool in = t < cnt;
        if (!__any_sync(FULLM, in)) break;
        bool valid = false;
        int ns = 0, nd = 0;
        if (in) {
            ns = map[srcP[t]];
            nd = map[dstP[t]];
            valid = (ns >= 0) && (nd >= 0);
        }
        unsigned m = __ballot_sync(FULLM, valid);
        if (m) {
            int leader = __ffs(m) - 1;
            int base = 0;
            if (lane == leader) base = atomicAdd(cntN, __popc(m));
            base = __shfl_sync(FULLM, base, leader);
            if (valid) {
                int off = __popc(m & ((1u << lane) - 1));
                srcN[base + off] = ns;
                dstN[base + off] = nd;
                atomicAdd(&deg[nd], 1);
            }
        }
    }
}

// block0 matmul: H[n,64] = X[n,3] @ W[3,64]; zero stats from block 0
__global__ void k_mm0(const float* __restrict__ X, const float* __restrict__ W,
                      float* __restrict__ H, float* __restrict__ stats, int n) {
    if (blockIdx.x == 0 && threadIdx.x < 128) stats[threadIdx.x] = 0.f;
    int t = blockIdx.x * blockDim.x + threadIdx.x;
    if (t >= n * 16) return;
    int r = t >> 4, q = (t & 15) * 4;
    const float* xp = X + (long long)r * 3;
    float a0 = 0.f, a1 = 0.f, a2 = 0.f, a3 = 0.f;
    #pragma unroll
    for (int k = 0; k < 3; k++) {
        float xv = xp[k];
        a0 += xv * __ldg(&W[k * HID + q]);
        a1 += xv * __ldg(&W[k * HID + q + 1]);
        a2 += xv * __ldg(&W[k * HID + q + 2]);
        a3 += xv * __ldg(&W[k * HID + q + 3]);
    }
    reinterpret_cast<float4*>(H)[(long long)r * 16 + (q >> 2)] = make_float4(a0, a1, a2, a3);
}

// pooled matmul: H = (X[perm[r]] * sc[r]) @ W ; 4 rows x 4 cols per thread
__global__ void k_mm_pool(const float* __restrict__ X, const float* __restrict__ W,
                          const int* __restrict__ perm, const float* __restrict__ sc,
                          float* __restrict__ H, float* __restrict__ stats, int n) {
    __shared__ float sW[HID * HID];
    for (int i = threadIdx.x; i < HID * HID; i += blockDim.x) sW[i] = W[i];
    if (blockIdx.x == 0 && threadIdx.x < 128) stats[threadIdx.x] = 0.f;
    __syncthreads();
    int t = blockIdx.x * blockDim.x + threadIdx.x;
    int rg = t >> 4, cg = t & 15;
    if (rg * 4 >= n) return;
    const float* xp[4];
    float s[4];
    #pragma unroll
    for (int i = 0; i < 4; i++) {
        int r = rg * 4 + i;
        xp[i] = X + (long long)perm[r] * HID;
        s[i] = sc[r];
    }
    float acc[4][4];
    #pragma unroll
    for (int i = 0; i < 4; i++)
        #pragma unroll
        for (int j = 0; j < 4; j++) acc[i][j] = 0.f;
    for (int k = 0; k < HID; k++) {
        float4 w = reinterpret_cast<const float4*>(sW)[k * 16 + cg];
        #pragma unroll
        for (int i = 0; i < 4; i++) {
            float xv = xp[i][k] * s[i];
            acc[i][0] += xv * w.x; acc[i][1] += xv * w.y;
            acc[i][2] += xv * w.z; acc[i][3] += xv * w.w;
        }
    }
    #pragma unroll
    for (int i = 0; i < 4; i++)
        reinterpret_cast<float4*>(H)[(long long)(rg * 4 + i) * 16 + cg] =
            make_float4(acc[i][0], acc[i][1], acc[i][2], acc[i][3]);
}

// up-path matmul with fused residual unpool: row = X[r] + (map[r]>=0 ? Xup[map[r]] : 0)
__global__ void k_mm_res(const float* __restrict__ X, const float* __restrict__ Xup,
                         const int* __restrict__ map, const float* __restrict__ W,
                         float* __restrict__ H, float* __restrict__ stats, int n) {
    __shared__ float sW[HID * HID];
    for (int i = threadIdx.x; i < HID * HID; i += blockDim.x) sW[i] = W[i];
    if (blockIdx.x == 0 && threadIdx.x < 128) stats[threadIdx.x] = 0.f;
    __syncthreads();
    int t = blockIdx.x * blockDim.x + threadIdx.x;
    int rg = t >> 4, cg = t & 15;
    if (rg * 4 >= n) return;
    const float* xp[4];
    const float* up[4];
    #pragma unroll
    for (int i = 0; i < 4; i++) {
        int r = rg * 4 + i;
        xp[i] = X + (long long)r * HID;
        int m = map[r];
        up[i] = (m >= 0) ? (Xup + (long long)m * HID) : nullptr;
    }
    float acc[4][4];
    #pragma unroll
    for (int i = 0; i < 4; i++)
        #pragma unroll
        for (int j = 0; j < 4; j++) acc[i][j] = 0.f;
    for (int k = 0; k < HID; k++) {
        float4 w = reinterpret_cast<const float4*>(sW)[k * 16 + cg];
        #pragma unroll
        for (int i = 0; i < 4; i++) {
            float xv = xp[i][k] + (up[i] ? up[i][k] : 0.f);
            acc[i][0] += xv * w.x; acc[i][1] += xv * w.y;
            acc[i][2] += xv * w.z; acc[i][3] += xv * w.w;
        }
    }
    #pragma unroll
    for (int i = 0; i < 4; i++)
        reinterpret_cast<float4*>(H)[(long long)(rg * 4 + i) * 16 + cg] =
            make_float4(acc[i][0], acc[i][1], acc[i][2], acc[i][3]);
}

// warp per dst row (grid-stride): Y[d] = sum cf*H[s] + fill*dinv[d]^2*H[d]; BN stats
__global__ void k_agg_bn(const int* __restrict__ rs, const int* __restrict__ csr,
                         const float* __restrict__ dinv, const float* __restrict__ H,
                         float* __restrict__ Y, float* __restrict__ stats,
                         float fill, int n) {
    __shared__ float sh[128];
    if (threadIdx.x < 128) sh[threadIdx.x] = 0.f;
    __syncthreads();
    int lane = threadIdx.x & 31;
    int w = (blockIdx.x * blockDim.x + threadIdx.x) >> 5;
    int nw = (gridDim.x * blockDim.x) >> 5;
    float s0 = 0.f, s1 = 0.f, q0 = 0.f, q1 = 0.f;
    for (int d = w; d < n; d += nw) {
        int r0 = rs[d], r1 = rs[d + 1];
        float dd = dinv[d];
        float a0 = 0.f, a1 = 0.f;
        int j = r0;
        for (; j + 2 <= r1; j += 2) {
            int sA = csr[j], sB = csr[j + 1];
            float cfA = dinv[sA] * dd;
            float cfB = dinv[sB] * dd;
            float2 hA = reinterpret_cast<const float2*>(H)[(long long)sA * 32 + lane];
            float2 hB = reinterpret_cast<const float2*>(H)[(long long)sB * 32 + lane];
            a0 += cfA * hA.x + cfB * hB.x;
            a1 += cfA * hA.y + cfB * hB.y;
        }
        if (j < r1) {
            int sA = csr[j];
            float cfA = dinv[sA] * dd;
            float2 hA = reinterpret_cast<const float2*>(H)[(long long)sA * 32 + lane];
            a0 += cfA * hA.x;
            a1 += cfA * hA.y;
        }
        float2 hd = reinterpret_cast<const float2*>(H)[(long long)d * 32 + lane];
        float sf = fill * dd * dd;
        float y0 = a0 + sf * hd.x;
        float y1 = a1 + sf * hd.y;
        reinterpret_cast<float2*>(Y)[(long long)d * 32 + lane] = make_float2(y0, y1);
        s0 += y0; s1 += y1; q0 += y0 * y0; q1 += y1 * y1;
    }
    atomicAdd(&sh[2 * lane],      s0);
    atomicAdd(&sh[2 * lane + 1],  s1);
    atomicAdd(&sh[64 + 2 * lane], q0);
    atomicAdd(&sh[65 + 2 * lane], q1);
    __syncthreads();
    if (threadIdx.x < 128) atomicAdd(&stats[threadIdx.x], sh[threadIdx.x]);
}

// plain BN + ReLU
__global__ void k_bn_relu(const float* __restrict__ Y, const float* __restrict__ gamma,
                          const float* __restrict__ beta, const float* __restrict__ stats,
                          float* __restrict__ Xo, int n) {
    float inv_n = 1.f / (float)n;
    int t = blockIdx.x * blockDim.x + threadIdx.x;
    if (t >= n * HID) return;
    int c = t & 63;
    float mu = stats[c] * inv_n;
    float var = stats[HID + c] * inv_n - mu * mu;
    float v = gamma[c] * (Y[t] - mu) * rsqrtf(var + BN_EPS) + beta[c];
    Xo[t] = v > 0.f ? v : 0.f;
}

// fused BN + ReLU + topk-score + idx init + next-level map/deg init
__global__ void k_bn_score(const float* __restrict__ Y, const float* __restrict__ gamma,
                           const float* __restrict__ beta, const float* __restrict__ stats,
                           float* __restrict__ Xo, const float* __restrict__ pw,
                           float* __restrict__ keys, int* __restrict__ idx,
                           int* __restrict__ map, int* __restrict__ deg, int n) {
    int gtid = blockIdx.x * blockDim.x + threadIdx.x;
    int stride = gridDim.x * blockDim.x;
    int lane = threadIdx.x & 31;
    float inv_n = 1.f / (float)n;
    // per-lane channels: c0 = lane, c1 = lane + 32
    float pa = pw[lane], pb = pw[lane + 32];
    float nv = pa * pa + pb * pb;
    #pragma unroll
    for (int o = 16; o > 0; o >>= 1) nv += __shfl_xor_sync(FULLM, nv, o);
    float rn = rsqrtf(nv);
    float mu0 = stats[lane] * inv_n;
    float var0 = stats[HID + lane] * inv_n - mu0 * mu0;
    float rs0_ = gamma[lane] * rsqrtf(var0 + BN_EPS);
    float b0 = beta[lane];
    float mu1 = stats[lane + 32] * inv_n;
    float var1 = stats[HID + lane + 32] * inv_n - mu1 * mu1;
    float rs1_ = gamma[lane + 32] * rsqrtf(var1 + BN_EPS);
    float b1 = beta[lane + 32];
    for (int r = gtid >> 5; r < n; r += stride >> 5) {
        float y0 = Y[(long long)r * HID + lane];
        float y1 = Y[(long long)r * HID + lane + 32];
        float x0 = fmaxf(rs0_ * (y0 - mu0) + b0, 0.f);
        float x1 = fmaxf(rs1_ * (y1 - mu1) + b1, 0.f);
        Xo[(long long)r * HID + lane] = x0;
        Xo[(long long)r * HID + lane + 32] = x1;
        float v = x0 * pa + x1 * pb;
        #pragma unroll
        for (int o = 16; o > 0; o >>= 1) v += __shfl_xor_sync(FULLM, v, o);
        if (lane == 0) {
            keys[r] = fmaxf(v * rn, 0.f);
            idx[r] = r;
        }
    }
    for (int t = gtid; t < n; t += stride) {
        map[t] = -1;
        deg[t] = 0;
    }
}

// final conv matmul (cout=1) with fused residual unpool
__global__ void k_mm1_res(const float* __restrict__ X, const float* __restrict__ Xup,
                          const int* __restrict__ map, const float* __restrict__ W,
                          float* __restrict__ h, int n) {
    __shared__ float sW[HID];
    if (threadIdx.x < HID) sW[threadIdx.x] = W[threadIdx.x];
    __syncthreads();
    int r = blockIdx.x * blockDim.x + threadIdx.x;
    if (r >= n) return;
    int m = map[r];
    const float* xp = X + (long long)r * HID;
    const float* up = (m >= 0) ? (Xup + (long long)m * HID) : nullptr;
    float acc = 0.f;
    #pragma unroll
    for (int k = 0; k < HID; k++) {
        float xv = xp[k] + (up ? up[k] : 0.f);
        acc += xv * sW[k];
    }
    h[r] = acc;
}

// out[d] = sigmoid(dinv[d]*sum(dinv[s]h[s]) + dinv[d]^2 h[d])
__global__ void k_csr_final(const int* __restrict__ rs, const int* __restrict__ csr,
                            const float* __restrict__ dinv, const float* __restrict__ h,
                            float* __restrict__ out, int n) {
    int lane = threadIdx.x & 31;
    int w = (blockIdx.x * blockDim.x + threadIdx.x) >> 5;
    int nw = (gridDim.x * blockDim.x) >> 5;
    for (int d = w; d < n; d += nw) {
        int r0 = rs[d], r1 = rs[d + 1];
        float acc = 0.f;
        for (int j = r0 + lane; j < r1; j += 32) {
            int s = csr[j];
            acc += dinv[s] * h[s];
        }
        #pragma unroll
        for (int o = 16; o > 0; o >>= 1) acc += __shfl_xor_sync(FULLM, acc, o);
        if (lane == 0) {
            float dd = dinv[d];
            float v = dd * acc + dd * dd * h[d];
            out[d] = 1.f / (1.f + expf(-v));
        }
    }
}

// ------------------------------- host side ---------------------------------
static inline int nblk(long long n) { return (int)((n + TPB - 1) / TPB); }

struct DevPtrs {
    float *X0, *X1, *X2, *XA, *XB, *H, *Y;
    int *deg, *cursor, *rs0, *rs1, *rs2, *rs3;
    float *dinv0_2, *dinv0_1, *dinv1, *dinv2, *dinv3;
    int *csr0, *csr1, *csr2, *csr3;
    int *src1, *dst1, *src2, *dst2, *src3, *dst3, *cnt;
    float *keys, *keysOut, *stats, *h1;
    int *idx, *perm0, *perm1, *perm2, *map0, *map1, *map2;
    void* cubtmp;
};

#define GETP(sym, field, type) { void* q; cudaGetSymbolAddress(&q, sym); p.field = (type)q; }

static void get_ptrs(DevPtrs& p) {
    GETP(g_X0, X0, float*) GETP(g_X1, X1, float*) GETP(g_X2, X2, float*)
    GETP(g_XA, XA, float*) GETP(g_XB, XB, float*) GETP(g_H, H, float*) GETP(g_Y, Y, float*)
    GETP(g_deg, deg, int*) GETP(g_cursor, cursor, int*)
    GETP(g_rs0, rs0, int*) GETP(g_rs1, rs1, int*) GETP(g_rs2, rs2, int*) GETP(g_rs3, rs3, int*)
    GETP(g_dinv0_2, dinv0_2, float*) GETP(g_dinv0_1, dinv0_1, float*)
    GETP(g_dinv1, dinv1, float*) GETP(g_dinv2, dinv2, float*) GETP(g_dinv3, dinv3, float*)
    GETP(g_csr0, csr0, int*) GETP(g_csr1, csr1, int*) GETP(g_csr2, csr2, int*) GETP(g_csr3, csr3, int*)
    GETP(g_src1, src1, int*) GETP(g_dst1, dst1, int*)
    GETP(g_src2, src2, int*) GETP(g_dst2, dst2, int*)
    GETP(g_src3, src3, int*) GETP(g_dst3, dst3, int*)
    GETP(g_cnt, cnt, int*)
    GETP(g_keys, keys, float*) GETP(g_keysOut, keysOut, float*)
    GETP(g_stats, stats, float*) GETP(g_h1, h1, float*)
    GETP(g_idx, idx, int*)
    GETP(g_perm0, perm0, int*) GETP(g_perm1, perm1, int*) GETP(g_perm2, perm2, int*)
    GETP(g_map0, map0, int*) GETP(g_map1, map1, int*) GETP(g_map2, map2, int*)
    GETP(g_cubtmp, cubtmp, void*)
}

static cudaStream_t s_side;
static cudaEvent_t  s_evF[5], s_evJ[5];
static bool s_init = false;

static void fork_side(int i) {
    cudaEventRecord(s_evF[i], 0);
    cudaStreamWaitEvent(s_side, s_evF[i], 0);
}
static void join_side(int i) {
    cudaEventRecord(s_evJ[i], s_side);
    cudaStreamWaitEvent(0, s_evJ[i], 0);
}

// side-stream CSR build from compacted (src,dst,cnt) + pre-histogrammed deg
static void csr_chain(const DevPtrs& p, const int* srcC, const int* dstC,
                      const int* cntp, int nfix, int n, int* rs, int* csr,
                      float* dinvA, float fillA, float* dinvB, float fillB) {
    size_t tb = 0;
    cub::DeviceScan::ExclusiveSum(nullptr, tb, p.deg, rs, n + 1, s_side);
    cub::DeviceScan::ExclusiveSum(p.cubtmp, tb, p.deg, rs, n + 1, s_side);
    k_prep<<<nblk(n), TPB, 0, s_side>>>(rs, p.cursor, dinvA, fillA, dinvB, fillB, n);
    k_scatter<<<GRIDE, TPB, 0, s_side>>>(srcC, dstC, p.cursor, csr, cntp, nfix);
}

static void radix_sort(const DevPtrs& p, int* permOut, int n) {
    size_t tb = 0;
    cub::DeviceRadixSort::SortPairsDescending(nullptr, tb, p.keys, p.keysOut,
                                              p.idx, permOut, n, 0, 32, (cudaStream_t)0);
    cub::DeviceRadixSort::SortPairsDescending(p.cubtmp, tb, p.keys, p.keysOut,
                                              p.idx, permOut, n, 0, 32, (cudaStream_t)0);
}

extern "C" void kernel_launch(void* const* d_in, const int* in_sizes, int n_in,
                              void* d_out, int out_size) {
    if (!s_init) {   // first call is the uncaptured correctness run
        cudaStreamCreateWithFlags(&s_side, cudaStreamNonBlocking);
        for (int i = 0; i < 5; i++) {
            cudaEventCreateWithFlags(&s_evF[i], cudaEventDisableTiming);
            cudaEventCreateWithFlags(&s_evJ[i], cudaEventDisableTiming);
        }
        s_init = true;
    }

    const float* x_in = (const float*)d_in[0];
    const int* ei     = (const int*)d_in[1];
    const int* src0 = ei;
    const int* dst0 = ei + cNE;
    const float* Wd[4] = {(const float*)d_in[2],  (const float*)d_in[5],
                          (const float*)d_in[8],  (const float*)d_in[11]};
    const float* gd[4] = {(const float*)d_in[3],  (const float*)d_in[6],
                          (const float*)d_in[9],  (const float*)d_in[12]};
    const float* bd[4] = {(const float*)d_in[4],  (const float*)d_in[7],
                          (const float*)d_in[10], (const float*)d_in[13]};
    const float* pw[3] = {(const float*)d_in[14], (const float*)d_in[15],
                          (const float*)d_in[16]};
    const float* Wu[2] = {(const float*)d_in[17], (const float*)d_in[20]};
    const float* gu[2] = {(const float*)d_in[18], (const float*)d_in[21]};
    const float* bu[2] = {(const float*)d_in[19], (const float*)d_in[22]};
    const float* Wout  = (const float*)d_in[23];

    DevPtrs p;
    get_ptrs(p);

    // ===== phase 0: block0 matmul || level-0 CSR build =====
    fork_side(0);
    k_zeroi<<<nblk(cN0 + 1), TPB, 0, s_side>>>(p.deg, cN0 + 1);
    k_hist0<<<GRIDE, TPB, 0, s_side>>>(dst0, p.deg);
    csr_chain(p, src0, dst0, nullptr, cNE, cN0, p.rs0, p.csr0,
              p.dinv0_2, 2.0f, p.dinv0_1, 1.0f);
    k_mm0<<<nblk((long long)cN0 * 16), TPB>>>(x_in, Wd[0], p.H, p.stats, cN0);
    join_side(0);
    k_agg_bn<<<2048, TPB>>>(p.rs0, p.csr0, p.dinv0_2, p.H, p.Y, p.stats, 2.0f, cN0);
    k_bn_score<<<2048, TPB>>>(p.Y, gd[0], bd[0], p.stats, p.X0, pw[0],
                              p.keys, p.idx, p.map0, p.deg, cN0);

    // ===== pool 0 + block 1 =====
    radix_sort(p, p.perm0, cN0);
    fork_side(1);
    k_mapset<<<nblk(cN1), TPB, 0, s_side>>>(p.map0, p.perm0, cN1, &p.cnt[0]);
    k_remap_hist<<<GRIDE, TPB, 0, s_side>>>(src0, dst0, p.map0, p.src1, p.dst1,
                                            &p.cnt[0], p.deg, nullptr, cNE);
    csr_chain(p, p.src1, p.dst1, &p.cnt[0], 0, cN1, p.rs1, p.csr1,
              p.dinv1, 2.0f, nullptr, 0.f);
    k_mm_pool<<<nblk((long long)cN1 * 4), TPB>>>(p.X0, Wd[1], p.perm0, p.keysOut,
                                                 p.H, p.stats, cN1);
    join_side(1);
    k_agg_bn<<<2048, TPB>>>(p.rs1, p.csr1, p.dinv1, p.H, p.Y, p.stats, 2.0f, cN1);
    k_bn_score<<<2048, TPB>>>(p.Y, gd[1], bd[1], p.stats, p.X1, pw[1],
                              p.keys, p.idx, p.map1, p.deg, cN1);

    // ===== pool 1 + block 2 =====
    radix_sort(p, p.perm1, cN1);
    fork_side(2);
    k_mapset<<<nblk(cN2), TPB, 0, s_side>>>(p.map1, p.perm1, cN2, &p.cnt[1]);
    k_remap_hist<<<GRIDE, TPB, 0, s_side>>>(p.src1, p.dst1, p.map1, p.src2, p.dst2,
                                            &p.cnt[1], p.deg, &p.cnt[0], 0);
    csr_chain(p, p.src2, p.dst2, &p.cnt[1], 0, cN2, p.rs2, p.csr2,
              p.dinv2, 2.0f, nullptr, 0.f);
    k_mm_pool<<<nblk((long long)cN2 * 4), TPB>>>(p.X1, Wd[2], p.perm1, p.keysOut,
                                                 p.H, p.stats, cN2);
    join_side(2);
    k_agg_bn<<<2048, TPB>>>(p.rs2, p.csr2, p.dinv2, p.H, p.Y, p.stats, 2.0f, cN2);
    k_bn_score<<<2048, TPB>>>(p.Y, gd[2], bd[2], p.stats, p.X2, pw[2],
                              p.keys, p.idx, p.map2, p.deg, cN2);

    // ===== pool 2 + block 3 =====
    radix_sort(p, p.perm2, cN2);
    fork_side(3);
    k_mapset<<<nblk(cN3), TPB, 0, s_side>>>(p.map2, p.perm2, cN3, &p.cnt[2]);
    k_remap_hist<<<GRIDE, TPB, 0, s_side>>>(p.src2, p.dst2, p.map2, p.src3, p.dst3,
                                            &p.cnt[2], p.deg, &p.cnt[1], 0);
    csr_chain(p, p.src3, p.dst3, &p.cnt[2], 0, cN3, p.rs3, p.csr3,
              p.dinv3, 2.0f, nullptr, 0.f);
    k_mm_pool<<<nblk((long long)cN3 * 4), TPB>>>(p.X2, Wd[3], p.perm2, p.keysOut,
                                                 p.H, p.stats, cN3);
    join_side(3);
    k_agg_bn<<<2048, TPB>>>(p.rs3, p.csr3, p.dinv3, p.H, p.Y, p.stats, 2.0f, cN3);
    k_bn_relu<<<nblk((long long)cN3 * HID), TPB>>>(p.Y, gd[3], bd[3], p.stats, p.XA, cN3);

    // ===== up path =====
    // up0: res = X2 + unpool(XA via map2), conv over level-2 CSR
    k_mm_res<<<nblk((long long)cN2 * 4), TPB>>>(p.X2, p.XA, p.map2, Wu[0],
                                                p.H, p.stats, cN2);
    k_agg_bn<<<2048, TPB>>>(p.rs2, p.csr2, p.dinv2, p.H, p.Y, p.stats, 2.0f, cN2);
    k_bn_relu<<<nblk((long long)cN2 * HID), TPB>>>(p.Y, gu[0], bu[0], p.stats, p.XB, cN2);

    // up1: res = X1 + unpool(XB via map1), conv over level-1 CSR
    k_mm_res<<<nblk((long long)cN1 * 4), TPB>>>(p.X1, p.XB, p.map1, Wu[1],
                                                p.H, p.stats, cN1);
    k_agg_bn<<<2048, TPB>>>(p.rs1, p.csr1, p.dinv1, p.H, p.Y, p.stats, 2.0f, cN1);
    k_bn_relu<<<nblk((long long)cN1 * HID), TPB>>>(p.Y, gu[1], bu[1], p.stats, p.XA, cN1);

    // final: res = X0 + unpool(XA via map0), 1-ch conv (fill=1) + sigmoid
    k_mm1_res<<<nblk(cN0), TPB>>>(p.X0, p.XA, p.map0, Wout, p.h1, cN0);
    k_csr_final<<<2048, TPB>>>(p.rs0, p.csr0, p.dinv0_1, p.h1, (float*)d_out, cN0);
}